// round 5
// baseline (speedup 1.0000x reference)
#include <cuda_runtime.h>
#include <cuda_bf16.h>

#define FULL_MASK 0xFFFFFFFFu
#define WPB 4          // warps per block (render)
#define K 8            // samples per lane per iteration -> 256 per warp-iter
#define NMAX 65536

// Segment start offsets: g_start[r] = first sample index of ray r, g_start[N] = M.
__device__ int g_start[NMAX + 1];

__device__ __forceinline__ float tanh_fast(float x) {
    float y;
    asm("tanh.approx.f32 %0, %1;" : "=f"(y) : "f"(x));
    return y;
}
// sigmoid(x) = 0.5*tanh(0.5x) + 0.5  (single MUFU)
__device__ __forceinline__ float sigmoid_fast(float x) {
    return fmaf(tanh_fast(0.5f * x), 0.5f, 0.5f);
}

// ---------------------------------------------------------------------------
// Kernel 1: boundary detection over the sorted ray_id array (int4 per thread).
// Writes g_start[r] for every boundary, covering empty rays; the thread at the
// array tail fills g_start[last+1 .. N] = M.
// ---------------------------------------------------------------------------
__global__ void __launch_bounds__(256)
boundary_kernel(const int* __restrict__ ray_id, int M, int N)
{
    const int t = blockIdx.x * blockDim.x + threadIdx.x;
    const int i = t * 4;
    if (i >= M) return;

    if (i + 4 <= M) {
        const int4 v = *(const int4*)(ray_id + i);
        const int a = (i == 0) ? -1 : __ldg(ray_id + i - 1);
        if (a   != v.x) for (int r = a   + 1; r <= v.x; r++) g_start[r] = i;
        if (v.x != v.y) for (int r = v.x + 1; r <= v.y; r++) g_start[r] = i + 1;
        if (v.y != v.z) for (int r = v.y + 1; r <= v.z; r++) g_start[r] = i + 2;
        if (v.z != v.w) for (int r = v.z + 1; r <= v.w; r++) g_start[r] = i + 3;
        if (i + 4 == M)
            for (int r = v.w + 1; r <= N; r++) g_start[r] = M;
    } else {
        int a = (i == 0) ? -1 : __ldg(ray_id + i - 1);
        for (int j = i; j < M; j++) {
            int b = __ldg(ray_id + j);
            if (a != b) for (int r = a + 1; r <= b; r++) g_start[r] = j;
            a = b;
        }
        for (int r = a + 1; r <= N; r++) g_start[r] = M;
    }
}

// ---------------------------------------------------------------------------
// Kernel 2: one warp per ray, K=8 samples per lane per iteration.
// Colors are folded into lane-local weighted sums BEFORE the warp scan, so
// only (P, vR, vG, vB) live across the shuffle chain.
//
// Math (interval = 0.5):
//   x  = density + shift
//   om = exp(-0.5*softplus(x)) = rsqrt(1 + e^x)
//   alpha = 1 - om = e^x * om^2 / (1 + om)      (cancellation-free)
//   w_j = carry * excl * q_j * alpha_j,  q_j = prod_{k<j} om_k (lane-local)
//   alphainv_last = final carry
// ---------------------------------------------------------------------------
__global__ void __launch_bounds__(WPB * 32)
render_kernel(const float* __restrict__ density,
              const float* __restrict__ rgb_raw,
              const float* __restrict__ shift,
              float*       __restrict__ out,
              int M, int N)
{
    const int warp = blockIdx.x * WPB + (threadIdx.x >> 5);
    if (warp >= N) return;
    const int lane = threadIdx.x & 31;
    const float shift0 = __ldg(shift);

    const int start = g_start[warp];
    const int end   = g_start[warp + 1];

    float carry = 1.0f;
    float accR = 0.0f, accG = 0.0f, accB = 0.0f;

    const int a0 = start & ~3;                 // float4-aligned loop base

    for (int itb = a0; itb < end; itb += 32 * K) {
        const int b = itb + K * lane;          // this lane's 8-sample base (4-aligned)
        // half-wise guards: addresses stay < M (end <= M, M % 4 == 0)
        const bool h1 = (b     < end) & (b + 4 > start);
        const bool h2 = (b + 4 < end) & (b + 8 > start);

        float d[K];
        float c[3 * K];
        #pragma unroll
        for (int j = 0; j < K; j++) d[j] = 0.f;
        #pragma unroll
        for (int j = 0; j < 3 * K; j++) c[j] = 0.f;

        if (h1) {
            const float4 d4 = __ldcs((const float4*)(density + b));
            d[0] = d4.x; d[1] = d4.y; d[2] = d4.z; d[3] = d4.w;
            const float4* rp = (const float4*)(rgb_raw + 3 * b);
            const float4 r0 = __ldcs(rp + 0);
            const float4 r1 = __ldcs(rp + 1);
            const float4 r2 = __ldcs(rp + 2);
            c[0]=r0.x; c[1]=r0.y; c[2] =r0.z; c[3] =r0.w; c[4] =r1.x; c[5] =r1.y;
            c[6]=r1.z; c[7]=r1.w; c[8] =r2.x; c[9] =r2.y; c[10]=r2.z; c[11]=r2.w;
        }
        if (h2) {
            const float4 d4 = __ldcs((const float4*)(density + b + 4));
            d[4] = d4.x; d[5] = d4.y; d[6] = d4.z; d[7] = d4.w;
            const float4* rp = (const float4*)(rgb_raw + 3 * (b + 4));
            const float4 r0 = __ldcs(rp + 0);
            const float4 r1 = __ldcs(rp + 1);
            const float4 r2 = __ldcs(rp + 2);
            c[12]=r0.x; c[13]=r0.y; c[14]=r0.z; c[15]=r0.w; c[16]=r1.x; c[17]=r1.y;
            c[18]=r1.z; c[19]=r1.w; c[20]=r2.x; c[21]=r2.y; c[22]=r2.z; c[23]=r2.w;
        }

        // fold colors into lane-local weighted sums; q accumulates lane prefix
        float q = 1.0f;
        float vR = 0.f, vG = 0.f, vB = 0.f;
        #pragma unroll
        for (int j = 0; j < K; j++) {
            const int idx = b + j;
            const bool valid = (idx >= start) & (idx < end);
            const float x  = d[j] + shift0;
            const float ex = __expf(fminf(x, 80.0f));           // no inf
            const float o  = rsqrtf(1.0f + ex);                 // om = exp(-s)
            const float a  = __fdividef(ex * o * o, 1.0f + o);  // 1-om, exact
            const float om = valid ? o : 1.0f;
            const float al = valid ? a : 0.0f;
            const float w  = al * q;                            // local weight
            vR = fmaf(w, sigmoid_fast(c[3*j + 0]), vR);
            vG = fmaf(w, sigmoid_fast(c[3*j + 1]), vG);
            vB = fmaf(w, sigmoid_fast(c[3*j + 2]), vB);
            q *= om;
        }

        // warp inclusive product scan of q (= per-lane total P)
        float p = q;
        #pragma unroll
        for (int dd = 1; dd < 32; dd <<= 1) {
            const float s = __shfl_up_sync(FULL_MASK, p, dd);
            if (lane >= dd) p *= s;
        }
        float excl = __shfl_up_sync(FULL_MASK, p, 1);
        if (lane == 0) excl = 1.0f;
        const float tot = __shfl_sync(FULL_MASK, p, 31);

        const float t = carry * excl;          // transmittance entering this lane
        accR = fmaf(t, vR, accR);
        accG = fmaf(t, vG, accG);
        accB = fmaf(t, vB, accB);
        carry *= tot;
    }

    // warp reduction of the color accumulators
    #pragma unroll
    for (int dd = 16; dd >= 1; dd >>= 1) {
        accR += __shfl_xor_sync(FULL_MASK, accR, dd);
        accG += __shfl_xor_sync(FULL_MASK, accG, dd);
        accB += __shfl_xor_sync(FULL_MASK, accB, dd);
    }

    if (lane == 0) {
        out[3 * warp + 0] = accR + carry;      // white background leftover
        out[3 * warp + 1] = accG + carry;
        out[3 * warp + 2] = accB + carry;
    }
}

extern "C" void kernel_launch(void* const* d_in, const int* in_sizes, int n_in,
                              void* d_out, int out_size)
{
    const float* density = (const float*)d_in[0];
    const float* rgb_raw = (const float*)d_in[1];
    const float* shift   = (const float*)d_in[2];
    const int*   ray_id  = (const int*)d_in[3];
    float*       out     = (float*)d_out;

    const int M = in_sizes[0];
    int N = out_size / 3;
    if (N > NMAX) N = NMAX;

    const int t1 = (M + 3) / 4;
    boundary_kernel<<<(t1 + 255) / 256, 256>>>(ray_id, M, N);

    const int blocks = (N + WPB - 1) / WPB;
    render_kernel<<<blocks, WPB * 32>>>(density, rgb_raw, shift, out, M, N);
}

// round 7
// speedup vs baseline: 1.1014x; 1.1014x over previous
#include <cuda_runtime.h>
#include <cuda_bf16.h>

#define FULL_MASK 0xFFFFFFFFu
#define WPB 8          // warps per block (render)
#define NMAX 65536

// Segment start offsets: g_start[r] = first sample index of ray r, g_start[N] = M.
__device__ int g_start[NMAX + 1];

__device__ __forceinline__ float tanh_fast(float x) {
    float y;
    asm("tanh.approx.f32 %0, %1;" : "=f"(y) : "f"(x));
    return y;
}
// sigmoid(x) = 0.5*tanh(0.5x) + 0.5  (single MUFU)
__device__ __forceinline__ float sigmoid_fast(float x) {
    return fmaf(tanh_fast(0.5f * x), 0.5f, 0.5f);
}

// ---------------------------------------------------------------------------
// Kernel 1: boundary detection over the sorted ray_id array (int4 per thread).
// Writes g_start[r] for every boundary (covers empty rays); the thread at the
// array tail fills g_start[last+1 .. N] = M.
// ---------------------------------------------------------------------------
__global__ void __launch_bounds__(256)
boundary_kernel(const int* __restrict__ ray_id, int M, int N)
{
    const int t = blockIdx.x * blockDim.x + threadIdx.x;
    const int i = t * 4;
    if (i >= M) return;

    if (i + 4 <= M) {
        const int4 v = *(const int4*)(ray_id + i);
        const int a = (i == 0) ? -1 : __ldg(ray_id + i - 1);
        if (a   != v.x) for (int r = a   + 1; r <= v.x; r++) g_start[r] = i;
        if (v.x != v.y) for (int r = v.x + 1; r <= v.y; r++) g_start[r] = i + 1;
        if (v.y != v.z) for (int r = v.y + 1; r <= v.z; r++) g_start[r] = i + 2;
        if (v.z != v.w) for (int r = v.z + 1; r <= v.w; r++) g_start[r] = i + 3;
        if (i + 4 == M)
            for (int r = v.w + 1; r <= N; r++) g_start[r] = M;
    } else {
        int a = (i == 0) ? -1 : __ldg(ray_id + i - 1);
        for (int j = i; j < M; j++) {
            int b = __ldg(ray_id + j);
            if (a != b) for (int r = a + 1; r <= b; r++) g_start[r] = j;
            a = b;
        }
        for (int r = a + 1; r <= N; r++) g_start[r] = M;
    }
}

// ---------------------------------------------------------------------------
// Kernel 2: one warp per ray. The ray's aligned quads [a0, a0+4G) are split
// contiguously across lanes (order preserved), each lane streams its own 1-3
// quads with unconditional float4 loads, and the warp does exactly ONE
// product scan per ray. Validity is folded into the density input:
// invalid sample -> x = -100 -> ex = 0 -> om = 1, alpha = 0.
//
// Math (interval = 0.5):
//   x  = density + shift
//   om = exp(-0.5*softplus(x)) = rsqrt(1 + e^x)
//   alpha = 1 - om = e^x * om^2 / (1 + om)      (cancellation-free)
//   out = sum(excl_lane * v_lane) + total_prod  (white background)
// ---------------------------------------------------------------------------
__global__ void __launch_bounds__(WPB * 32)
render_kernel(const float* __restrict__ density,
              const float* __restrict__ rgb_raw,
              const float* __restrict__ shift,
              float*       __restrict__ out,
              int M, int N)
{
    const int warp = blockIdx.x * WPB + (threadIdx.x >> 5);
    if (warp >= N) return;
    const int lane = threadIdx.x & 31;
    const float shift0 = __ldg(shift);

    const int start = g_start[warp];
    const int end   = g_start[warp + 1];

    const int a0 = start & ~3;                    // 4-aligned base
    const int G  = (end - a0 + 3) >> 2;           // number of quads (may be 0)
    const int g0 = (lane * G)       >> 5;         // this lane's quad range
    const int g1 = ((lane + 1) * G) >> 5;         // contiguous, order-preserving

    // unsigned-trick segment test: valid <=> (unsigned)(idx-start) < len
    const unsigned len = (unsigned)(end - start);

    float q  = 1.0f;                              // lane-local product of om
    float vR = 0.f, vG = 0.f, vB = 0.f;           // lane-local weighted colors

    for (int g = g0; g < g1; ++g) {
        const int b = a0 + (g << 2);              // quad base; b+4 <= M (M%4==0)
        const float4 d4 = __ldcs((const float4*)(density + b));
        const float4* rp = (const float4*)(rgb_raw + 3 * b);
        const float4 r0 = __ldcs(rp + 0);
        const float4 r1 = __ldcs(rp + 1);
        const float4 r2 = __ldcs(rp + 2);

        const float dv[4] = { d4.x, d4.y, d4.z, d4.w };
        const float cc[12] = { r0.x, r0.y, r0.z, r0.w, r1.x, r1.y,
                               r1.z, r1.w, r2.x, r2.y, r2.z, r2.w };

        #pragma unroll
        for (int j = 0; j < 4; ++j) {
            const bool valid = (unsigned)(b + j - start) < len;
            // invalid -> x=-100 -> ex=0 -> om=1, alpha=0 (no extra selects)
            const float x  = valid ? fminf(dv[j] + shift0, 80.0f) : -100.0f;
            const float ex = __expf(x);
            const float o  = rsqrtf(1.0f + ex);                 // om = exp(-s)
            const float a  = __fdividef(ex * o * o, 1.0f + o);  // 1-om, exact
            const float w  = a * q;                             // local weight
            vR = fmaf(w, sigmoid_fast(cc[3*j + 0]), vR);
            vG = fmaf(w, sigmoid_fast(cc[3*j + 1]), vG);
            vB = fmaf(w, sigmoid_fast(cc[3*j + 2]), vB);
            q *= o;
        }
    }

    // ONE warp inclusive product scan of q per ray
    float p = q;
    #pragma unroll
    for (int dd = 1; dd < 32; dd <<= 1) {
        const float s = __shfl_up_sync(FULL_MASK, p, dd);
        if (lane >= dd) p *= s;
    }
    float excl = __shfl_up_sync(FULL_MASK, p, 1);
    if (lane == 0) excl = 1.0f;
    const float tot = __shfl_sync(FULL_MASK, p, 31);  // alphainv_last

    float accR = excl * vR;
    float accG = excl * vG;
    float accB = excl * vB;

    #pragma unroll
    for (int dd = 16; dd >= 1; dd >>= 1) {
        accR += __shfl_xor_sync(FULL_MASK, accR, dd);
        accG += __shfl_xor_sync(FULL_MASK, accG, dd);
        accB += __shfl_xor_sync(FULL_MASK, accB, dd);
    }

    if (lane == 0) {
        out[3 * warp + 0] = accR + tot;           // white background leftover
        out[3 * warp + 1] = accG + tot;
        out[3 * warp + 2] = accB + tot;
    }
}

extern "C" void kernel_launch(void* const* d_in, const int* in_sizes, int n_in,
                              void* d_out, int out_size)
{
    const float* density = (const float*)d_in[0];
    const float* rgb_raw = (const float*)d_in[1];
    const float* shift   = (const float*)d_in[2];
    const int*   ray_id  = (const int*)d_in[3];
    float*       out     = (float*)d_out;

    const int M = in_sizes[0];
    int N = out_size / 3;
    if (N > NMAX) N = NMAX;

    const int t1 = (M + 3) / 4;
    boundary_kernel<<<(t1 + 255) / 256, 256>>>(ray_id, M, N);

    const int blocks = (N + WPB - 1) / WPB;
    render_kernel<<<blocks, WPB * 32>>>(density, rgb_raw, shift, out, M, N);
}